// round 5
// baseline (speedup 1.0000x reference)
#include <cuda_runtime.h>
#include <math.h>

#define LQ      5
#define H       100
#define NB      24
#define TOK     (NB * LQ)          // 120 tokens / CTA
#define THREADS 320
#define ACTIVE  300                // 25 col-groups x 12 row-groups (10 tokens each)
#define LD      100                // x-tile row stride (floats)
#define LDW     128                // W-chunk row stride (floats, line-aligned)
#define KC      20                 // K rows per W chunk

#define SMEM_FLOATS (4 * TOK * LD + 2 * KC * LDW + TOK * LQ)
#define SMEM_BYTES  (SMEM_FLOATS * 4 + NB * 4)

typedef unsigned long long u64;

__device__ __forceinline__ u64 pack2(float x) {
    unsigned int u = __float_as_uint(x);
    u64 r;
    asm("mov.b64 %0, {%1, %1};" : "=l"(r) : "r"(u));
    return r;
}
__device__ __forceinline__ void ffma2(u64& acc, u64 a, u64 b) {
    asm("fma.rn.f32x2 %0, %1, %2, %0;" : "+l"(acc) : "l"(a), "l"(b));
}
__device__ __forceinline__ void unpack2(u64 v, float& lo, float& hi) {
    unsigned int a, b;
    asm("mov.b64 {%0, %1}, %2;" : "=r"(a), "=r"(b) : "l"(v));
    lo = __uint_as_float(a); hi = __uint_as_float(b);
}

__device__ __forceinline__ void cp16(void* dst_smem, const void* src_gmem) {
    unsigned int d = (unsigned int)__cvta_generic_to_shared(dst_smem);
    asm volatile("cp.async.cg.shared.global [%0], [%1], 16;" :: "r"(d), "l"(src_gmem));
}
__device__ __forceinline__ void cp_commit() { asm volatile("cp.async.commit_group;"); }
__device__ __forceinline__ void cp_wait0()  { asm volatile("cp.async.wait_group 0;"); }

// Prefetch one KC x H chunk of W into a line-aligned smem buffer.
__device__ __forceinline__ void prefetch_w(float* s_wbuf, const float* gW, int tid) {
    #pragma unroll 1
    for (int t = tid; t < KC * (H / 4); t += THREADS) {
        int row = t / (H / 4);
        int q   = t - row * (H / 4);
        cp16(s_wbuf + row * LDW + q * 4, gW + row * H + q * 4);
    }
    cp_commit();
}

#define ZERO_ACC()                                  \
    _Pragma("unroll")                               \
    for (int i = 0; i < 10; i++) { acc[i][0] = 0ull; acc[i][1] = 0ull; }

// One K-chunk (KC rows) of FFMA2 GEMM on a 10-token x 4-col thread tile.
// XV_STMT sets float4 xv using (i, kk, koff).
#define GEMM_CHUNK(SW, XV_STMT)                                           \
    _Pragma("unroll")                                                     \
    for (int kk = 0; kk < KC; kk += 4) {                                  \
        ulonglong2 w0 = *(const ulonglong2*)((SW) + (kk + 0) * LDW + c0); \
        ulonglong2 w1 = *(const ulonglong2*)((SW) + (kk + 1) * LDW + c0); \
        ulonglong2 w2 = *(const ulonglong2*)((SW) + (kk + 2) * LDW + c0); \
        ulonglong2 w3 = *(const ulonglong2*)((SW) + (kk + 3) * LDW + c0); \
        _Pragma("unroll")                                                 \
        for (int i = 0; i < 10; i++) {                                    \
            float4 xv; XV_STMT;                                           \
            u64 p0 = pack2(xv.x), p1 = pack2(xv.y);                       \
            u64 p2 = pack2(xv.z), p3 = pack2(xv.w);                       \
            ffma2(acc[i][0], p0, w0.x); ffma2(acc[i][1], p0, w0.y);       \
            ffma2(acc[i][0], p1, w1.x); ffma2(acc[i][1], p1, w1.y);       \
            ffma2(acc[i][0], p2, w2.x); ffma2(acc[i][1], p2, w2.y);       \
            ffma2(acc[i][0], p3, w3.x); ffma2(acc[i][1], p3, w3.y);       \
        }                                                                 \
    }

#define PIPE_STEP() { cp_wait0(); __syncthreads(); }

__global__ __launch_bounds__(THREADS, 1)
void reading_memory_kernel(const float* __restrict__ sub_emb,
                           const float* __restrict__ memory,
                           const int*   __restrict__ sub_len,
                           const float* __restrict__ sub_raw,
                           const float* __restrict__ W_mem,
                           const float* __restrict__ b_mem,
                           const float* __restrict__ W_sub,
                           const float* __restrict__ b_sub,
                           const float* __restrict__ W_gate,
                           const float* __restrict__ b_gate,
                           float* __restrict__ out, int Btot)
{
    extern __shared__ float smem[];
    float* s_mem = smem;                   // [120][100] memory
    float* s_sub = s_mem + TOK * LD;       // [120][100] sub_emb
    float* s_c   = s_sub + TOK * LD;       // [120][100] raw -> sub_4att
    float* s_d   = s_c   + TOK * LD;       // [120][100] mem_4att -> sub_mem
    float* s_w0  = s_d   + TOK * LD;       // [20][128] W chunk buf 0
    float* s_w1  = s_w0  + KC * LDW;       // [20][128] W chunk buf 1
    float* s_att = s_w1  + KC * LDW;       // [120][5]
    int*   s_len = (int*)(s_att + TOK * LQ);
    float* s_wb[2] = { s_w0, s_w1 };

    const int tid = threadIdx.x;
    const int b0  = blockIdx.x * NB;
    const int nb  = (Btot - b0 < NB) ? (Btot - b0) : NB;
    const int ntok = nb * LQ;

    // Kick off W chunk 0 prefetch before anything else.
    prefetch_w(s_w0, W_mem, tid);
    int pb = 0;

    // ---------------- Stage input tiles ----------------
    {
        const size_t base = (size_t)b0 * LQ * H;
        const float4* g_m = (const float4*)(memory  + base);
        const float4* g_s = (const float4*)(sub_emb + base);
        const float4* g_r = (const float4*)(sub_raw + base);
        const int nv = ntok * H / 4;
        #pragma unroll 1
        for (int t = tid; t < TOK * H / 4; t += THREADS) {
            int flat = t * 4;
            int row = flat / H, col = flat - row * H;
            float4 m, s, r;
            if (t < nv) { m = g_m[t]; s = g_s[t]; r = g_r[t]; }
            else        { m = s = r = make_float4(0.f, 0.f, 0.f, 0.f); }
            *(float4*)(s_mem + row * LD + col) = m;
            *(float4*)(s_sub + row * LD + col) = s;
            *(float4*)(s_c   + row * LD + col) = r;
        }
        if (tid < NB) s_len[tid] = (tid < nb) ? sub_len[b0 + tid] : 0;
    }

    const int tx = tid % 25;
    const int ty = tid / 25;          // row-group: 10 tokens = 2 batches
    const int c0 = tx * 4;
    const int r0 = ty * 10;
    const bool act = (tid < ACTIVE);

    u64 acc[10][2];

    // ---------------- GEMM1: mem_4att = tanh(memory @ W_mem + b) -> s_d ----------------
    ZERO_ACC();
    for (int c = 0; c < 5; c++) {
        PIPE_STEP();   // chunk c ready in s_wb[pb]; also the first one is the staging barrier
        if (c < 4)      prefetch_w(s_wb[pb ^ 1], W_mem + (c + 1) * KC * H, tid);
        else            prefetch_w(s_wb[pb ^ 1], W_sub, tid);
        if (act) {
            const int k0 = c * KC;
            GEMM_CHUNK(s_wb[pb], xv = *(const float4*)(s_mem + (r0 + i) * LD + k0 + kk));
        }
        pb ^= 1;
    }
    if (act) {
        float4 bv = *(const float4*)(b_mem + c0);
        #pragma unroll
        for (int i = 0; i < 10; i++) {
            float a0, a1, a2, a3;
            unpack2(acc[i][0], a0, a1); unpack2(acc[i][1], a2, a3);
            float4 o = make_float4(tanhf(a0 + bv.x), tanhf(a1 + bv.y),
                                   tanhf(a2 + bv.z), tanhf(a3 + bv.w));
            *(float4*)(s_d + (r0 + i) * LD + c0) = o;
        }
    }

    // ---------------- GEMM2: sub_4att = tanh([sub|raw] @ W_sub + b) -> s_c ----------------
    ZERO_ACC();
    for (int c = 0; c < 10; c++) {
        PIPE_STEP();
        if (c < 9)      prefetch_w(s_wb[pb ^ 1], W_sub + (c + 1) * KC * H, tid);
        else            prefetch_w(s_wb[pb ^ 1], W_gate, tid);
        if (act) {
            const float* xb = (c < 5) ? s_sub : s_c;
            const int koff = (c < 5) ? c * KC : (c - 5) * KC;
            GEMM_CHUNK(s_wb[pb], xv = *(const float4*)(xb + (r0 + i) * LD + koff + kk));
        }
        pb ^= 1;
    }
    __syncthreads();   // all raw reads done before overwriting s_c with sub_4att
    if (act) {
        float4 bv = *(const float4*)(b_sub + c0);
        #pragma unroll
        for (int i = 0; i < 10; i++) {
            float a0, a1, a2, a3;
            unpack2(acc[i][0], a0, a1); unpack2(acc[i][1], a2, a3);
            float4 o = make_float4(tanhf(a0 + bv.x), tanhf(a1 + bv.y),
                                   tanhf(a2 + bv.z), tanhf(a3 + bv.w));
            *(float4*)(s_c + (r0 + i) * LD + c0) = o;
        }
    }
    __syncthreads();

    // ---------------- Attention logits: one (q, key) per thread ----------------
    #pragma unroll 1
    for (int p = tid; p < TOK * LQ; p += THREADS) {
        const int q  = p / LQ;
        const int ke = p - q * LQ;
        const int bt = q / LQ;
        const float4* aq = (const float4*)(s_c + q * LD);
        const float4* ak = (const float4*)(s_d + (bt * LQ + ke) * LD);
        float d = 0.f;
        #pragma unroll
        for (int t = 0; t < H / 4; t++) {
            float4 a = aq[t], b = ak[t];
            d += a.x * b.x + a.y * b.y + a.z * b.z + a.w * b.w;
        }
        s_att[p] = d;
    }
    __syncthreads();

    // ---------------- Softmax over keys + query-row mask ----------------
    if (tid < TOK) {
        const int bt = tid / LQ;
        const int ql = tid - bt * LQ;
        float* row = s_att + tid * LQ;
        if (ql >= s_len[bt]) {
            #pragma unroll
            for (int k = 0; k < LQ; k++) row[k] = 0.f;
        } else {
            float m = row[0];
            #pragma unroll
            for (int k = 1; k < LQ; k++) m = fmaxf(m, row[k]);
            float e[LQ], s = 0.f;
            #pragma unroll
            for (int k = 0; k < LQ; k++) { e[k] = expf(row[k] - m); s += e[k]; }
            float inv = 1.f / s;
            #pragma unroll
            for (int k = 0; k < LQ; k++) row[k] = e[k] * inv;
        }
    }
    __syncthreads();

    // ---------------- sub_mem = att @ memory -> s_d (m4a dead) ----------------
    if (act) {
        #pragma unroll
        for (int sb = 0; sb < 2; sb++) {
            const int tb = r0 + sb * LQ;     // token base of this batch
            float4 mv[5];
            #pragma unroll
            for (int k = 0; k < 5; k++)
                mv[k] = *(const float4*)(s_mem + (tb + k) * LD + c0);
            #pragma unroll
            for (int i = 0; i < 5; i++) {
                const float* a = s_att + (tb + i) * LQ;
                float4 o;
                o.x = a[0]*mv[0].x + a[1]*mv[1].x + a[2]*mv[2].x + a[3]*mv[3].x + a[4]*mv[4].x;
                o.y = a[0]*mv[0].y + a[1]*mv[1].y + a[2]*mv[2].y + a[3]*mv[3].y + a[4]*mv[4].y;
                o.z = a[0]*mv[0].z + a[1]*mv[1].z + a[2]*mv[2].z + a[3]*mv[3].z + a[4]*mv[4].z;
                o.w = a[0]*mv[0].w + a[1]*mv[1].w + a[2]*mv[2].w + a[3]*mv[3].w + a[4]*mv[4].w;
                *(float4*)(s_d + (tb + i) * LD + c0) = o;
            }
        }
    }
    __syncthreads();

    // ---------------- GEMM3: g = sigmoid([sub | sub_mem | sub*sub_mem] @ W_gate + b) ----------------
    ZERO_ACC();
    for (int c = 0; c < 15; c++) {
        PIPE_STEP();
        if (c < 14) prefetch_w(s_wb[pb ^ 1], W_gate + (c + 1) * KC * H, tid);
        if (act) {
            const int seg  = c / 5;
            const int koff = (c - seg * 5) * KC;
            if (seg == 0) {
                GEMM_CHUNK(s_wb[pb],
                    xv = *(const float4*)(s_sub + (r0 + i) * LD + koff + kk));
            } else if (seg == 1) {
                GEMM_CHUNK(s_wb[pb],
                    xv = *(const float4*)(s_d + (r0 + i) * LD + koff + kk));
            } else {
                GEMM_CHUNK(s_wb[pb],
                    float4 xa = *(const float4*)(s_sub + (r0 + i) * LD + koff + kk);
                    float4 xb = *(const float4*)(s_d   + (r0 + i) * LD + koff + kk);
                    xv = make_float4(xa.x * xb.x, xa.y * xb.y, xa.z * xb.z, xa.w * xb.w));
            }
        }
        pb ^= 1;
    }

    // ---------------- Gated output ----------------
    if (act) {
        float4 bv = *(const float4*)(b_gate + c0);
        #pragma unroll
        for (int sb = 0; sb < 2; sb++) {
            if (2 * ty + sb >= nb) break;
            const size_t ob = (size_t)(b0 + 2 * ty + sb) * LQ * H;
            #pragma unroll
            for (int i = 0; i < 5; i++) {
                const int r = sb * 5 + i;
                float a0, a1, a2, a3;
                unpack2(acc[r][0], a0, a1); unpack2(acc[r][1], a2, a3);
                float4 e = *(const float4*)(s_sub + (r0 + r) * LD + c0);
                float4 m = *(const float4*)(s_d   + (r0 + r) * LD + c0);
                float g0 = 1.f / (1.f + expf(-(a0 + bv.x)));
                float g1 = 1.f / (1.f + expf(-(a1 + bv.y)));
                float g2 = 1.f / (1.f + expf(-(a2 + bv.z)));
                float g3 = 1.f / (1.f + expf(-(a3 + bv.w)));
                float4 o = make_float4((1.f - g0) * e.x + g0 * m.x,
                                       (1.f - g1) * e.y + g1 * m.y,
                                       (1.f - g2) * e.z + g2 * m.z,
                                       (1.f - g3) * e.w + g3 * m.w);
                *(float4*)(out + ob + i * H + c0) = o;
            }
        }
    }
}

extern "C" void kernel_launch(void* const* d_in, const int* in_sizes, int n_in,
                              void* d_out, int out_size)
{
    const float* sub_emb = (const float*)d_in[0];
    const float* memory  = (const float*)d_in[1];
    const int*   sub_len = (const int*)  d_in[2];
    const float* sub_raw = (const float*)d_in[3];
    const float* W_mem   = (const float*)d_in[4];
    const float* b_mem   = (const float*)d_in[5];
    const float* W_sub   = (const float*)d_in[6];
    const float* b_sub   = (const float*)d_in[7];
    const float* W_gate  = (const float*)d_in[8];
    const float* b_gate  = (const float*)d_in[9];
    float* out = (float*)d_out;

    const int Btot = in_sizes[0] / (LQ * H);
    const int grid = (Btot + NB - 1) / NB;

    cudaFuncSetAttribute(reading_memory_kernel,
                         cudaFuncAttributeMaxDynamicSharedMemorySize, SMEM_BYTES);
    reading_memory_kernel<<<grid, THREADS, SMEM_BYTES>>>(
        sub_emb, memory, sub_len, sub_raw,
        W_mem, b_mem, W_sub, b_sub, W_gate, b_gate, out, Btot);
}

// round 9
// speedup vs baseline: 1.0764x; 1.0764x over previous
#include <cuda_runtime.h>
#include <math.h>

#define LQ      5
#define H       100
#define NB      12
#define TOK     (NB * LQ)          // 60 tokens / CTA
#define THREADS 320                // 10 warps: 2 row-blocks x 5 col-blocks
#define KC      20                 // K rows per W chunk
#define TILE    (TOK * H)          // 6000 floats, flat (LD == H == 100)
#define WBUF    (KC * H)           // 2000 floats per W buffer

#define SMEM_FLOATS (4 * TILE + 2 * WBUF + TOK * LQ)
#define SMEM_BYTES  (SMEM_FLOATS * 4 + NB * 4)   // 113,248 B -> 2 CTAs/SM

typedef unsigned long long u64;

__device__ __forceinline__ u64 pack2(float x) {
    unsigned int u = __float_as_uint(x);
    u64 r;
    asm("mov.b64 %0, {%1, %1};" : "=l"(r) : "r"(u));
    return r;
}
__device__ __forceinline__ void ffma2(u64& acc, u64 a, u64 b) {
    asm("fma.rn.f32x2 %0, %1, %2, %0;" : "+l"(acc) : "l"(a), "l"(b));
}
__device__ __forceinline__ void unpack2(u64 v, float& lo, float& hi) {
    unsigned int a, b;
    asm("mov.b64 {%0, %1}, %2;" : "=r"(a), "=r"(b) : "l"(v));
    lo = __uint_as_float(a); hi = __uint_as_float(b);
}
__device__ __forceinline__ void cp16(void* dst_smem, const void* src_gmem) {
    unsigned int d = (unsigned int)__cvta_generic_to_shared(dst_smem);
    asm volatile("cp.async.cg.shared.global [%0], [%1], 16;" :: "r"(d), "l"(src_gmem));
}
__device__ __forceinline__ void cp_commit() { asm volatile("cp.async.commit_group;"); }
__device__ __forceinline__ void cp_wait0()  { asm volatile("cp.async.wait_group 0;"); }

// W chunk is KC*H contiguous floats -> flat async copy.
__device__ __forceinline__ void prefetch_w(float* s, const float* g, int tid) {
    #pragma unroll 1
    for (int t = tid; t < WBUF / 4; t += THREADS)
        cp16(s + t * 4, g + t * 4);
    cp_commit();
}

#define ZERO_ACC()                                  \
    _Pragma("unroll")                               \
    for (int i = 0; i < 5; i++) { acc[i][0] = 0ull; acc[i][1] = 0ull; }

// One KC-row chunk of FFMA2 GEMM on a 5-token x 4-col thread tile.
// XV_STMT sets float4 xv using (i, kk) and the chunk's base offset.
#define GEMM_CHUNK(SW, XV_STMT)                                           \
    _Pragma("unroll")                                                     \
    for (int kk = 0; kk < KC; kk += 4) {                                  \
        ulonglong2 w0 = *(const ulonglong2*)((SW) + (kk + 0) * H + c0);   \
        ulonglong2 w1 = *(const ulonglong2*)((SW) + (kk + 1) * H + c0);   \
        ulonglong2 w2 = *(const ulonglong2*)((SW) + (kk + 2) * H + c0);   \
        ulonglong2 w3 = *(const ulonglong2*)((SW) + (kk + 3) * H + c0);   \
        _Pragma("unroll")                                                 \
        for (int i = 0; i < 5; i++) {                                     \
            float4 xv; XV_STMT;                                           \
            u64 p0 = pack2(xv.x), p1 = pack2(xv.y);                       \
            u64 p2 = pack2(xv.z), p3 = pack2(xv.w);                       \
            ffma2(acc[i][0], p0, w0.x); ffma2(acc[i][1], p0, w0.y);       \
            ffma2(acc[i][0], p1, w1.x); ffma2(acc[i][1], p1, w1.y);       \
            ffma2(acc[i][0], p2, w2.x); ffma2(acc[i][1], p2, w2.y);       \
            ffma2(acc[i][0], p3, w3.x); ffma2(acc[i][1], p3, w3.y);       \
        }                                                                 \
    }

#define PIPE_STEP() { cp_wait0(); __syncthreads(); }

__global__ __launch_bounds__(THREADS, 2)
void reading_memory_kernel(const float* __restrict__ sub_emb,
                           const float* __restrict__ memory,
                           const int*   __restrict__ sub_len,
                           const float* __restrict__ sub_raw,
                           const float* __restrict__ W_mem,
                           const float* __restrict__ b_mem,
                           const float* __restrict__ W_sub,
                           const float* __restrict__ b_sub,
                           const float* __restrict__ W_gate,
                           const float* __restrict__ b_gate,
                           float* __restrict__ out, int Btot)
{
    extern __shared__ float smem[];
    float* s_mem = smem;               // [60][100] memory
    float* s_sub = s_mem + TILE;       // [60][100] sub_emb
    float* s_c   = s_sub + TILE;       // [60][100] raw -> sub_4att
    float* s_d   = s_c   + TILE;       // [60][100] mem_4att -> sub_mem
    float* s_w0  = s_d   + TILE;       // [20][100] W chunk buf 0
    float* s_w1  = s_w0  + WBUF;       // [20][100] W chunk buf 1
    float* s_att = s_w1  + WBUF;       // [60][5]
    int*   s_len = (int*)(s_att + TOK * LQ);
    float* s_wb[2] = { s_w0, s_w1 };

    const int tid = threadIdx.x;
    const int b0  = blockIdx.x * NB;
    const int nb  = (Btot - b0 < NB) ? (Btot - b0) : NB;
    const int ntok = nb * LQ;

    // Kick off W chunk 0 prefetch before anything else.
    prefetch_w(s_w0, W_mem, tid);
    int pb = 0;

    // ---------------- Stage input tiles (flat: LD == H) ----------------
    {
        const size_t base = (size_t)b0 * LQ * H;
        const float4* g_m = (const float4*)(memory  + base);
        const float4* g_s = (const float4*)(sub_emb + base);
        const float4* g_r = (const float4*)(sub_raw + base);
        const int nv = ntok * H / 4;
        #pragma unroll 1
        for (int t = tid; t < TILE / 4; t += THREADS) {
            float4 m, s, r;
            if (t < nv) { m = g_m[t]; s = g_s[t]; r = g_r[t]; }
            else        { m = s = r = make_float4(0.f, 0.f, 0.f, 0.f); }
            ((float4*)s_mem)[t] = m;
            ((float4*)s_sub)[t] = s;
            ((float4*)s_c)[t]   = r;
        }
        if (tid < NB) s_len[tid] = (tid < nb) ? sub_len[b0 + tid] : 0;
    }

    // Warp-aligned mapping: warp = (row-block, col-block); lane = (rg, cg).
    const int wid  = tid / 32, lane = tid % 32;
    const int wr   = wid / 5,  wc   = wid % 5;     // wr 0..1, wc 0..4
    const int rg   = lane / 5, cg   = lane % 5;    // 30 active lanes
    const bool act = (lane < 30);
    const int r0   = wr * 30 + rg * 5;             // 5 tokens = 1 batch
    const int c0   = wc * 20 + cg * 4;             // 4 cols

    u64 acc[5][2];

    // ---------------- GEMM1: mem_4att = tanh(memory @ W_mem + b) -> s_d ----------------
    ZERO_ACC();
    for (int c = 0; c < 5; c++) {
        PIPE_STEP();     // chunk c ready (first step also guards input staging)
        if (c < 4) prefetch_w(s_wb[pb ^ 1], W_mem + (c + 1) * KC * H, tid);
        else       prefetch_w(s_wb[pb ^ 1], W_sub, tid);
        if (act) {
            const int k0 = c * KC;
            GEMM_CHUNK(s_wb[pb], xv = *(const float4*)(s_mem + (r0 + i) * H + k0 + kk));
        }
        pb ^= 1;
    }
    if (act) {
        float4 bv = *(const float4*)(b_mem + c0);
        #pragma unroll
        for (int i = 0; i < 5; i++) {
            float a0, a1, a2, a3;
            unpack2(acc[i][0], a0, a1); unpack2(acc[i][1], a2, a3);
            float4 o = make_float4(tanhf(a0 + bv.x), tanhf(a1 + bv.y),
                                   tanhf(a2 + bv.z), tanhf(a3 + bv.w));
            *(float4*)(s_d + (r0 + i) * H + c0) = o;
        }
    }

    // ---------------- GEMM2: sub_4att = tanh([sub|raw] @ W_sub + b) -> s_c ----------------
    ZERO_ACC();
    for (int c = 0; c < 10; c++) {
        PIPE_STEP();
        if (c < 9) prefetch_w(s_wb[pb ^ 1], W_sub + (c + 1) * KC * H, tid);
        else       prefetch_w(s_wb[pb ^ 1], W_gate, tid);
        if (act) {
            const float* xb = (c < 5) ? s_sub : s_c;
            const int koff = (c < 5) ? c * KC : (c - 5) * KC;
            GEMM_CHUNK(s_wb[pb], xv = *(const float4*)(xb + (r0 + i) * H + koff + kk));
        }
        pb ^= 1;
    }
    __syncthreads();   // all raw reads done before overwriting s_c with sub_4att
    if (act) {
        float4 bv = *(const float4*)(b_sub + c0);
        #pragma unroll
        for (int i = 0; i < 5; i++) {
            float a0, a1, a2, a3;
            unpack2(acc[i][0], a0, a1); unpack2(acc[i][1], a2, a3);
            float4 o = make_float4(tanhf(a0 + bv.x), tanhf(a1 + bv.y),
                                   tanhf(a2 + bv.z), tanhf(a3 + bv.w));
            *(float4*)(s_c + (r0 + i) * H + c0) = o;
        }
    }
    __syncthreads();

    // ---------------- Attention logits: one (q, key) per thread ----------------
    if (tid < TOK * LQ) {
        const int q  = tid / LQ;
        const int ke = tid - q * LQ;
        const int bt = q / LQ;
        const float4* aq = (const float4*)(s_c + q * H);
        const float4* ak = (const float4*)(s_d + (bt * LQ + ke) * H);
        float d = 0.f;
        #pragma unroll
        for (int t = 0; t < H / 4; t++) {
            float4 a = aq[t], b = ak[t];
            d += a.x * b.x + a.y * b.y + a.z * b.z + a.w * b.w;
        }
        s_att[tid] = d;
    }
    __syncthreads();

    // ---------------- Softmax over keys + query-row mask ----------------
    if (tid < TOK) {
        const int bt = tid / LQ;
        const int ql = tid - bt * LQ;
        float* row = s_att + tid * LQ;
        if (ql >= s_len[bt]) {
            #pragma unroll
            for (int k = 0; k < LQ; k++) row[k] = 0.f;
        } else {
            float m = row[0];
            #pragma unroll
            for (int k = 1; k < LQ; k++) m = fmaxf(m, row[k]);
            float e[LQ], s = 0.f;
            #pragma unroll
            for (int k = 0; k < LQ; k++) { e[k] = expf(row[k] - m); s += e[k]; }
            float inv = 1.f / s;
            #pragma unroll
            for (int k = 0; k < LQ; k++) row[k] = e[k] * inv;
        }
    }
    __syncthreads();

    // ---------------- sub_mem = att @ memory -> s_d (m4a dead) ----------------
    if (act) {
        float4 mv[5];
        #pragma unroll
        for (int k = 0; k < 5; k++)
            mv[k] = *(const float4*)(s_mem + (r0 + k) * H + c0);
        #pragma unroll
        for (int i = 0; i < 5; i++) {
            const float* a = s_att + (r0 + i) * LQ;
            float4 o;
            o.x = a[0]*mv[0].x + a[1]*mv[1].x + a[2]*mv[2].x + a[3]*mv[3].x + a[4]*mv[4].x;
            o.y = a[0]*mv[0].y + a[1]*mv[1].y + a[2]*mv[2].y + a[3]*mv[3].y + a[4]*mv[4].y;
            o.z = a[0]*mv[0].z + a[1]*mv[1].z + a[2]*mv[2].z + a[3]*mv[3].z + a[4]*mv[4].z;
            o.w = a[0]*mv[0].w + a[1]*mv[1].w + a[2]*mv[2].w + a[3]*mv[3].w + a[4]*mv[4].w;
            *(float4*)(s_d + (r0 + i) * H + c0) = o;
        }
    }
    __syncthreads();

    // ---------------- GEMM3: g = sigmoid([sub | sub_mem | sub*sub_mem] @ W_gate + b) ----------------
    ZERO_ACC();
    for (int c = 0; c < 15; c++) {
        PIPE_STEP();
        if (c < 14) prefetch_w(s_wb[pb ^ 1], W_gate + (c + 1) * KC * H, tid);
        if (act) {
            const int seg  = c / 5;
            const int koff = (c - seg * 5) * KC;
            if (seg == 0) {
                GEMM_CHUNK(s_wb[pb],
                    xv = *(const float4*)(s_sub + (r0 + i) * H + koff + kk));
            } else if (seg == 1) {
                GEMM_CHUNK(s_wb[pb],
                    xv = *(const float4*)(s_d + (r0 + i) * H + koff + kk));
            } else {
                GEMM_CHUNK(s_wb[pb],
                    float4 xa = *(const float4*)(s_sub + (r0 + i) * H + koff + kk);
                    float4 xb = *(const float4*)(s_d   + (r0 + i) * H + koff + kk);
                    xv = make_float4(xa.x * xb.x, xa.y * xb.y, xa.z * xb.z, xa.w * xb.w));
            }
        }
        pb ^= 1;
    }

    // ---------------- Gated output ----------------
    if (act && (r0 / LQ) < nb) {
        float4 bv = *(const float4*)(b_gate + c0);
        const size_t ob = (size_t)(b0 + r0 / LQ) * LQ * H;
        #pragma unroll
        for (int i = 0; i < 5; i++) {
            float a0, a1, a2, a3;
            unpack2(acc[i][0], a0, a1); unpack2(acc[i][1], a2, a3);
            float4 e = *(const float4*)(s_sub + (r0 + i) * H + c0);
            float4 m = *(const float4*)(s_d   + (r0 + i) * H + c0);
            float g0 = 1.f / (1.f + expf(-(a0 + bv.x)));
            float g1 = 1.f / (1.f + expf(-(a1 + bv.y)));
            float g2 = 1.f / (1.f + expf(-(a2 + bv.z)));
            float g3 = 1.f / (1.f + expf(-(a3 + bv.w)));
            float4 o = make_float4((1.f - g0) * e.x + g0 * m.x,
                                   (1.f - g1) * e.y + g1 * m.y,
                                   (1.f - g2) * e.z + g2 * m.z,
                                   (1.f - g3) * e.w + g3 * m.w);
            *(float4*)(out + ob + i * H + c0) = o;
        }
    }
}

extern "C" void kernel_launch(void* const* d_in, const int* in_sizes, int n_in,
                              void* d_out, int out_size)
{
    const float* sub_emb = (const float*)d_in[0];
    const float* memory  = (const float*)d_in[1];
    const int*   sub_len = (const int*)  d_in[2];
    const float* sub_raw = (const float*)d_in[3];
    const float* W_mem   = (const float*)d_in[4];
    const float* b_mem   = (const float*)d_in[5];
    const float* W_sub   = (const float*)d_in[6];
    const float* b_sub   = (const float*)d_in[7];
    const float* W_gate  = (const float*)d_in[8];
    const float* b_gate  = (const float*)d_in[9];
    float* out = (float*)d_out;

    const int Btot = in_sizes[0] / (LQ * H);
    const int grid = (Btot + NB - 1) / NB;

    cudaFuncSetAttribute(reading_memory_kernel,
                         cudaFuncAttributeMaxDynamicSharedMemorySize, SMEM_BYTES);
    reading_memory_kernel<<<grid, THREADS, SMEM_BYTES>>>(
        sub_emb, memory, sub_len, sub_raw,
        W_mem, b_mem, W_sub, b_sub, W_gate, b_gate, out, Btot);
}